// round 5
// baseline (speedup 1.0000x reference)
#include <cuda_runtime.h>
#include <math.h>
#include <stdint.h>

#define B 256
#define T 512
#define F 128
#define H 256
#define H3 768
#define BH (B * H)

// Static device scratch for the hoisted input projection: MX[t*B+b][0..767]
__device__ float g_mx[(size_t)T * B * H3];   // ~402 MB

// ---------------------------------------------------------------------------
// f32x2 packed-FMA helpers (FFMA2 — only reachable via PTX fma.rn.f32x2)
// ---------------------------------------------------------------------------
__device__ __forceinline__ void ffma2(unsigned long long &acc,
                                      unsigned long long a,
                                      unsigned long long b) {
    asm("fma.rn.f32x2 %0, %1, %2, %0;" : "+l"(acc) : "l"(a), "l"(b));
}
__device__ __forceinline__ unsigned long long dup2(float v) {
    unsigned long long r;
    asm("mov.b64 %0, {%1, %1};" : "=l"(r) : "f"(v));
    return r;
}
__device__ __forceinline__ float2 unpk(unsigned long long v) {
    float2 r;
    asm("mov.b64 {%0, %1}, %2;" : "=f"(r.x), "=f"(r.y) : "l"(v));
    return r;
}
__device__ __forceinline__ float tanh_fast(float x) {
    float y;
    asm("tanh.approx.f32 %0, %1;" : "=f"(y) : "f"(x));
    return y;
}
__device__ __forceinline__ float sig_fast(float x) {
    return fmaf(0.5f, tanh_fast(0.5f * x), 0.5f);
}
__device__ __forceinline__ uint32_t smem_u32(const void* p) {
    uint32_t a;
    asm("{ .reg .u64 t; cvta.to.shared.u64 t, %1; cvt.u32.u64 %0, t; }"
        : "=r"(a) : "l"(p));
    return a;
}
__device__ __forceinline__ void st_cluster_f32(uint32_t saddr, int rank, float v) {
    uint32_t r;
    asm volatile("mapa.shared::cluster.u32 %0, %1, %2;" : "=r"(r) : "r"(saddr), "r"(rank));
    asm volatile("st.shared::cluster.f32 [%0], %1;" :: "r"(r), "f"(v));
}

// ---------------------------------------------------------------------------
// Kernel 1: MX[m, n] = x[b, t, :] @ W[:, n] + bias_in[n],  m = t*B + b
// ---------------------------------------------------------------------------
#define GM_BM 64
#define GM_BN 64
#define GM_BK 32

__global__ __launch_bounds__(256) void mx_gemm(const float* __restrict__ x,
                                               const float* __restrict__ w,
                                               const float* __restrict__ bias) {
    __shared__ float As[GM_BK][GM_BM + 4];
    __shared__ float Bs[GM_BK][GM_BN];

    const int bm = blockIdx.y * GM_BM;
    const int bn = blockIdx.x * GM_BN;
    const int tid = (int)threadIdx.x;
    const int tm = (tid >> 4) << 2;
    const int tn = (tid & 15) << 2;

    unsigned long long acc2[4][2];
    #pragma unroll
    for (int i = 0; i < 4; i++) { acc2[i][0] = 0ull; acc2[i][1] = 0ull; }

    for (int k0 = 0; k0 < F; k0 += GM_BK) {
        #pragma unroll
        for (int i = 0; i < 2; i++) {
            int idx = tid + i * 256;
            int r = idx >> 3;
            int c = (idx & 7) << 2;
            int m = bm + r;
            int t = m >> 8;
            int b = m & 255;
            float4 v = *(const float4*)&x[((size_t)b * T + t) * F + k0 + c];
            As[c + 0][r] = v.x;
            As[c + 1][r] = v.y;
            As[c + 2][r] = v.z;
            As[c + 3][r] = v.w;
        }
        #pragma unroll
        for (int i = 0; i < 2; i++) {
            int idx = tid + i * 256;
            int r = idx >> 4;
            int c = (idx & 15) << 2;
            *(float4*)&Bs[r][c] = *(const float4*)&w[(size_t)(k0 + r) * H3 + bn + c];
        }
        __syncthreads();

        #pragma unroll
        for (int k = 0; k < GM_BK; k++) {
            unsigned long long a0 = dup2(As[k][tm + 0]);
            unsigned long long a1 = dup2(As[k][tm + 1]);
            unsigned long long a2 = dup2(As[k][tm + 2]);
            unsigned long long a3 = dup2(As[k][tm + 3]);
            const unsigned long long* bsk = (const unsigned long long*)&Bs[k][tn];
            unsigned long long b01 = bsk[0];
            unsigned long long b23 = bsk[1];
            ffma2(acc2[0][0], a0, b01); ffma2(acc2[0][1], a0, b23);
            ffma2(acc2[1][0], a1, b01); ffma2(acc2[1][1], a1, b23);
            ffma2(acc2[2][0], a2, b01); ffma2(acc2[2][1], a2, b23);
            ffma2(acc2[3][0], a3, b01); ffma2(acc2[3][1], a3, b23);
        }
        __syncthreads();
    }

    float4 bz4 = *(const float4*)&bias[bn + tn];
    #pragma unroll
    for (int i = 0; i < 4; i++) {
        float2 lo = unpk(acc2[i][0]);
        float2 hi = unpk(acc2[i][1]);
        float4 o;
        o.x = lo.x + bz4.x;
        o.y = lo.y + bz4.y;
        o.z = hi.x + bz4.z;
        o.w = hi.y + bz4.w;
        *(float4*)&g_mx[(size_t)(bm + tm + i) * H3 + bn + tn] = o;
    }
}

// ---------------------------------------------------------------------------
// Kernel 2: persistent GRU recurrence, cluster/DSMEM version.
// Grid (8 j-tiles, 16 b-tiles) = 128 blocks, cluster (8,1,1) along j.
// 512 threads, 1 block/SM. Block owns a (16 batch x 32 hidden) tile for
// all 512 steps. Wr slice (256k x 96 gate-cols, 98KB) cached in smem once.
// h exchanged via DSMEM (each block writes its tile into all 8 peers'
// double-buffered hs), one cluster barrier per step. No global h reads.
// ---------------------------------------------------------------------------
#define BT 16
#define JT 32
#define NKG 8                       // k-split groups (512 threads / 64)
#define WS_FLOATS (256 * 96)
#define HSS 264                     // h row stride (16B aligned, bank skew)
#define HS_FLOATS (BT * HSS)
#define PT_FLOATS (NKG * BT * 96)
#define SMEM_FLOATS (WS_FLOATS + 2 * HS_FLOATS + PT_FLOATS)
#define SMEM_BYTES (SMEM_FLOATS * 4)

extern __shared__ float smem_dyn[];

__global__ __launch_bounds__(512, 1) __cluster_dims__(8, 1, 1)
void gru_persist(const float* __restrict__ mx,
                 const float* __restrict__ wr,
                 const float* __restrict__ rbias,
                 float* __restrict__ out) {
    float* ws  = smem_dyn;                        // [k=256][96]
    float* hsA = ws + WS_FLOATS;                  // [16][HSS]
    float* hsB = hsA + HS_FLOATS;                 // [16][HSS]
    float* pt  = hsB + HS_FLOATS;                 // [kg=8][16][96]

    const int tid = (int)threadIdx.x;             // 0..511
    const int jb = (int)blockIdx.x;               // 0..7 == cluster rank
    const int ib = (int)blockIdx.y;               // 0..15
    const int b0 = ib * BT;
    const int j0 = jb * JT;

    // Phase-A mapping: 8 k-groups x 64 threads; thread = 2 b-rows x 4 j x 3 gates
    const int kg = tid >> 6;                      // 0..7
    const int r6 = tid & 63;
    const int bqa = r6 >> 3;                      // 0..7
    const int jqa = (r6 & 7) << 2;                // 0,4,...,28

    // Phase-C mapping: one (b, j) element per thread
    const int bc = tid >> 5;                      // 0..15
    const int jc = tid & 31;                      // 0..31

    // Load Wr slice once
    for (int idx = tid; idx < WS_FLOATS / 2; idx += 512) {
        int k = idx / 48;
        int c2 = idx % 48;
        int g = c2 >> 4;
        int jj = (c2 & 15) << 1;
        float2 v = *(const float2*)&wr[(size_t)k * H3 + g * H + j0 + jj];
        *(float2*)&ws[k * 96 + g * 32 + jj] = v;
    }

    // Recurrent bias for phase-C column
    const float bz = rbias[j0 + jc];
    const float br = rbias[H + j0 + jc];
    const float bh = rbias[2 * H + j0 + jc];

    // Zero both h buffers
    for (int i = tid; i < 2 * HS_FLOATS; i += 512) hsA[i] = 0.0f;
    __syncthreads();
    asm volatile("barrier.cluster.arrive.aligned;" ::: "memory");
    asm volatile("barrier.cluster.wait.aligned;" ::: "memory");

    // smem address (for mapa) of this thread's phase-C h element, both buffers
    const uint32_t myA = smem_u32(&hsA[bc * HSS + j0 + jc]);
    const uint32_t myB = smem_u32(&hsB[bc * HSS + j0 + jc]);

    for (int t = 0; t < T; t++) {
        const float* hcur = (t & 1) ? hsB : hsA;
        const uint32_t dstAddr = (t & 1) ? myA : myB;   // write into the other buffer

        // ---- prefetch mx gate inputs (global, off dependency chain) ----
        const float* mxr = mx + ((size_t)t * B + (b0 + bc)) * H3 + (j0 + jc);
        float xz = mxr[0];
        float xr = mxr[H];
        float xh = mxr[2 * H];

        // ---- phase A: partial mh over this k-group's 32 k's ----
        unsigned long long acc[2][3][2];
        #pragma unroll
        for (int bb = 0; bb < 2; bb++)
            #pragma unroll
            for (int g = 0; g < 3; g++) { acc[bb][g][0] = 0ull; acc[bb][g][1] = 0ull; }

        const float* h0p = hcur + (2 * bqa) * HSS;
        const float* h1p = hcur + (2 * bqa + 1) * HSS;
        const int k_beg = kg * 32;

        #pragma unroll 8
        for (int kk = 0; kk < 32; kk++) {
            int k = k_beg + kk;
            const float* wk = ws + k * 96 + jqa;
            ulonglong2 wz = *(const ulonglong2*)(wk);
            ulonglong2 wv = *(const ulonglong2*)(wk + 32);
            ulonglong2 wh = *(const ulonglong2*)(wk + 64);
            unsigned long long h0 = dup2(h0p[k]);
            unsigned long long h1 = dup2(h1p[k]);
            ffma2(acc[0][0][0], h0, wz.x); ffma2(acc[0][0][1], h0, wz.y);
            ffma2(acc[0][1][0], h0, wv.x); ffma2(acc[0][1][1], h0, wv.y);
            ffma2(acc[0][2][0], h0, wh.x); ffma2(acc[0][2][1], h0, wh.y);
            ffma2(acc[1][0][0], h1, wz.x); ffma2(acc[1][0][1], h1, wz.y);
            ffma2(acc[1][1][0], h1, wv.x); ffma2(acc[1][1][1], h1, wv.y);
            ffma2(acc[1][2][0], h1, wh.x); ffma2(acc[1][2][1], h1, wh.y);
        }

        #pragma unroll
        for (int bb = 0; bb < 2; bb++) {
            float* pr = pt + ((kg * BT + 2 * bqa + bb) * 96) + jqa;
            #pragma unroll
            for (int g = 0; g < 3; g++) {
                ulonglong2 v;
                v.x = acc[bb][g][0];
                v.y = acc[bb][g][1];
                *(ulonglong2*)(pr + g * 32) = v;
            }
        }
        __syncthreads();

        // ---- phase C: reduce 8 partials, gates, h_new ----
        float mz = 0.f, mr = 0.f, mh = 0.f;
        #pragma unroll
        for (int g2 = 0; g2 < NKG; g2++) {
            const float* p = pt + (g2 * BT + bc) * 96 + jc;
            mz += p[0];
            mr += p[32];
            mh += p[64];
        }
        float hp = hcur[bc * HSS + j0 + jc];
        float z = sig_fast(xz + mz + bz);
        float r = sig_fast(xr + mr + br);
        float c = tanh_fast(xh + r * (mh + bh));
        float o = c + z * (hp - c);

        // ---- broadcast h_new to all 8 cluster peers' next buffer ----
        #pragma unroll
        for (int p = 0; p < 8; p++) st_cluster_f32(dstAddr, p, o);

        // ---- cluster barrier; output STG hides between arrive and wait ----
        __syncthreads();   // all threads' DSMEM stores issued before arrive
        asm volatile("barrier.cluster.arrive.aligned;" ::: "memory");
        out[(size_t)t * BH + (size_t)(b0 + bc) * H + j0 + jc] = o;
        asm volatile("barrier.cluster.wait.aligned;" ::: "memory");
    }
}

// ---------------------------------------------------------------------------
// Launch
// ---------------------------------------------------------------------------
extern "C" void kernel_launch(void* const* d_in, const int* in_sizes, int n_in,
                              void* d_out, int out_size) {
    (void)in_sizes; (void)n_in; (void)out_size;
    const float* x    = (const float*)d_in[0];   // (B, T, F)
    const float* w    = (const float*)d_in[1];   // (F, 3H)
    const float* wr   = (const float*)d_in[2];   // (H, 3H)
    const float* bias = (const float*)d_in[3];   // (2, 3H)
    float* out = (float*)d_out;                  // (T, B, H)

    static int attr_set = 0;
    if (!attr_set) {
        cudaFuncSetAttribute(gru_persist,
                             cudaFuncAttributeMaxDynamicSharedMemorySize,
                             SMEM_BYTES);
        attr_set = 1;
    }

    float* mx;
    cudaGetSymbolAddress((void**)&mx, g_mx);

    dim3 g1(H3 / GM_BN, (T * B) / GM_BM);        // (12, 2048)
    mx_gemm<<<g1, 256>>>(x, w, bias);

    const float* rbias = bias + H3;
    dim3 g2(8, 16);                              // 128 blocks, clusters of 8 on x
    gru_persist<<<g2, 512, SMEM_BYTES>>>(mx, wr, rbias, out);
}

// round 6
// speedup vs baseline: 1.5558x; 1.5558x over previous
#include <cuda_runtime.h>
#include <math.h>
#include <stdint.h>

#define B 256
#define T 512
#define F 128
#define H 256
#define H3 768
#define BH (B * H)

// Static device scratch for the hoisted input projection: MX[t*B+b][0..767]
__device__ float g_mx[(size_t)T * B * H3];   // ~402 MB

// Flag array for inter-block sync (one 128B line per flag)
#define NJB 8
#define NBB 16
__device__ unsigned g_flags[NBB][NJB * 32];

// ---------------------------------------------------------------------------
// f32x2 packed-FMA helpers (FFMA2 — only reachable via PTX fma.rn.f32x2)
// ---------------------------------------------------------------------------
__device__ __forceinline__ void ffma2(unsigned long long &acc,
                                      unsigned long long a,
                                      unsigned long long b) {
    asm("fma.rn.f32x2 %0, %1, %2, %0;" : "+l"(acc) : "l"(a), "l"(b));
}
__device__ __forceinline__ unsigned long long dup2(float v) {
    unsigned long long r;
    asm("mov.b64 %0, {%1, %1};" : "=l"(r) : "f"(v));
    return r;
}
__device__ __forceinline__ float2 unpk(unsigned long long v) {
    float2 r;
    asm("mov.b64 {%0, %1}, %2;" : "=f"(r.x), "=f"(r.y) : "l"(v));
    return r;
}
__device__ __forceinline__ float tanh_fast(float x) {
    float y;
    asm("tanh.approx.f32 %0, %1;" : "=f"(y) : "f"(x));
    return y;
}
__device__ __forceinline__ float sig_fast(float x) {
    return fmaf(0.5f, tanh_fast(0.5f * x), 0.5f);
}
__device__ __forceinline__ unsigned ld_acq(const unsigned* p) {
    unsigned v;
    asm volatile("ld.acquire.gpu.global.u32 %0, [%1];" : "=r"(v) : "l"(p));
    return v;
}

// ---------------------------------------------------------------------------
// Kernel 1: MX[m, n] = x[b, t, :] @ W[:, n] + bias_in[n],  m = t*B + b
// ---------------------------------------------------------------------------
#define GM_BM 64
#define GM_BN 64
#define GM_BK 32

__global__ __launch_bounds__(256) void mx_gemm(const float* __restrict__ x,
                                               const float* __restrict__ w,
                                               const float* __restrict__ bias) {
    __shared__ float As[GM_BK][GM_BM + 4];
    __shared__ float Bs[GM_BK][GM_BN];

    const int bm = blockIdx.y * GM_BM;
    const int bn = blockIdx.x * GM_BN;
    const int tid = (int)threadIdx.x;
    const int tm = (tid >> 4) << 2;
    const int tn = (tid & 15) << 2;

    unsigned long long acc2[4][2];
    #pragma unroll
    for (int i = 0; i < 4; i++) { acc2[i][0] = 0ull; acc2[i][1] = 0ull; }

    for (int k0 = 0; k0 < F; k0 += GM_BK) {
        #pragma unroll
        for (int i = 0; i < 2; i++) {
            int idx = tid + i * 256;
            int r = idx >> 3;
            int c = (idx & 7) << 2;
            int m = bm + r;
            int t = m >> 8;
            int b = m & 255;
            float4 v = *(const float4*)&x[((size_t)b * T + t) * F + k0 + c];
            As[c + 0][r] = v.x;
            As[c + 1][r] = v.y;
            As[c + 2][r] = v.z;
            As[c + 3][r] = v.w;
        }
        #pragma unroll
        for (int i = 0; i < 2; i++) {
            int idx = tid + i * 256;
            int r = idx >> 4;
            int c = (idx & 15) << 2;
            *(float4*)&Bs[r][c] = *(const float4*)&w[(size_t)(k0 + r) * H3 + bn + c];
        }
        __syncthreads();

        #pragma unroll
        for (int k = 0; k < GM_BK; k++) {
            unsigned long long a0 = dup2(As[k][tm + 0]);
            unsigned long long a1 = dup2(As[k][tm + 1]);
            unsigned long long a2 = dup2(As[k][tm + 2]);
            unsigned long long a3 = dup2(As[k][tm + 3]);
            const unsigned long long* bsk = (const unsigned long long*)&Bs[k][tn];
            unsigned long long b01 = bsk[0];
            unsigned long long b23 = bsk[1];
            ffma2(acc2[0][0], a0, b01); ffma2(acc2[0][1], a0, b23);
            ffma2(acc2[1][0], a1, b01); ffma2(acc2[1][1], a1, b23);
            ffma2(acc2[2][0], a2, b01); ffma2(acc2[2][1], a2, b23);
            ffma2(acc2[3][0], a3, b01); ffma2(acc2[3][1], a3, b23);
        }
        __syncthreads();
    }

    float4 bz4 = *(const float4*)&bias[bn + tn];
    #pragma unroll
    for (int i = 0; i < 4; i++) {
        float2 lo = unpk(acc2[i][0]);
        float2 hi = unpk(acc2[i][1]);
        float4 o;
        o.x = lo.x + bz4.x;
        o.y = lo.y + bz4.y;
        o.z = hi.x + bz4.z;
        o.w = hi.y + bz4.w;
        *(float4*)&g_mx[(size_t)(bm + tm + i) * H3 + bn + tn] = o;
    }
}

// ---------------------------------------------------------------------------
// Kernel 2: persistent GRU recurrence, chunked-arrival version.
// Grid (8 j-tiles, 16 b-tiles) = 128 blocks, 512 threads, 1 block/SM.
// Block owns a (16 batch x 32 hidden) tile for all 512 steps.
// Wr slice (256k x 96 gate-cols, 96KB) in smem once.
// Phase A consumes h in per-peer 32-k chunks: own chunk first (no wait),
// then peers in rotated order, spinning on each peer's flag just-in-time.
// h loads are 2x LDG.128 per thread per chunk, straight into registers.
// 8-way k-split over threads; partials reduced once via smem.
// ---------------------------------------------------------------------------
#define BT 16
#define JT 32
#define WS_FLOATS (256 * 96)
#define PT_FLOATS (8 * BT * 96)
#define SMEM_BYTES ((WS_FLOATS + PT_FLOATS) * 4)

extern __shared__ float smem_dyn[];

__global__ __launch_bounds__(512, 1)
void gru_persist(const float* __restrict__ mx,
                 const float* __restrict__ wr,
                 const float* __restrict__ rbias,
                 float* __restrict__ out) {
    float* ws = smem_dyn;                         // [k=256][96]
    float* pt = ws + WS_FLOATS;                   // [kg=8][16][96]

    const int tid = (int)threadIdx.x;             // 0..511
    const int jb = (int)blockIdx.x;               // 0..7
    const int ib = (int)blockIdx.y;               // 0..15
    const int b0 = ib * BT;
    const int j0 = jb * JT;

    // Phase-A mapping: kg 0..7 (4 k's per chunk), 2 b-rows x 4 j x 3 gates
    const int kg = tid >> 6;                      // 0..7
    const int r6 = tid & 63;
    const int bqa = r6 >> 3;                      // 0..7
    const int jqa = (r6 & 7) << 2;                // 0,4,...,28

    // Phase-C mapping: one (b, j) element per thread
    const int bc = tid >> 5;                      // 0..15
    const int jc = tid & 31;                      // 0..31

    // Load Wr slice once: ws[k][g*32+jj] = wr[k][g*256 + j0 + jj]
    for (int idx = tid; idx < WS_FLOATS / 2; idx += 512) {
        int k = idx / 48;
        int c2 = idx % 48;
        int g = c2 >> 4;
        int jj = (c2 & 15) << 1;
        float2 v = *(const float2*)&wr[(size_t)k * H3 + g * H + j0 + jj];
        *(float2*)&ws[k * 96 + g * 32 + jj] = v;
    }

    const float bz = rbias[j0 + jc];
    const float br = rbias[H + j0 + jc];
    const float bh = rbias[2 * H + j0 + jc];
    __syncthreads();

    float hp = 0.0f;                              // carried own h element

    for (int t = 0; t < T; t++) {
        // ---- prefetch mx gate inputs (off dependency chain) ----
        const float* mxr = mx + ((size_t)t * B + (b0 + bc)) * H3 + (j0 + jc);
        float xz = mxr[0];
        float xr = mxr[H];
        float xh = mxr[2 * H];

        unsigned long long acc[2][3][2];
        #pragma unroll
        for (int bb = 0; bb < 2; bb++)
            #pragma unroll
            for (int g = 0; g < 3; g++) { acc[bb][g][0] = 0ull; acc[bb][g][1] = 0ull; }

        if (t > 0) {
            const float* hprev = out + (size_t)(t - 1) * BH;
            const float* r0p = hprev + (size_t)(b0 + 2 * bqa) * H;
            const float* r1p = r0p + H;
            const int colbase = kg * 4;

            // chunk 0 = own j-tile: produced by this block last step, no wait
            float4 acur = *(const float4*)&r0p[j0 + colbase];
            float4 bcur = *(const float4*)&r1p[j0 + colbase];

            #pragma unroll
            for (int c = 0; c < 8; c++) {
                float4 anxt, bnxt;
                if (c < 7) {
                    const int pn = (jb + c + 1) & 7;
                    const unsigned* fp = &g_flags[ib][pn * 32];
                    while (ld_acq(fp) < (unsigned)t) { __nanosleep(20); }
                    anxt = *(const float4*)&r0p[pn * 32 + colbase];
                    bnxt = *(const float4*)&r1p[pn * 32 + colbase];
                } else {
                    anxt = acur; bnxt = bcur;     // unused
                }

                const int peer = (jb + c) & 7;
                const float* wbase = ws + (size_t)(peer * 32 + kg * 4) * 96 + jqa;
                float ha[4] = {acur.x, acur.y, acur.z, acur.w};
                float hb[4] = {bcur.x, bcur.y, bcur.z, bcur.w};
                #pragma unroll
                for (int kk = 0; kk < 4; kk++) {
                    const float* wk = wbase + kk * 96;
                    ulonglong2 wz = *(const ulonglong2*)(wk);
                    ulonglong2 wv = *(const ulonglong2*)(wk + 32);
                    ulonglong2 wh = *(const ulonglong2*)(wk + 64);
                    unsigned long long h0 = dup2(ha[kk]);
                    unsigned long long h1 = dup2(hb[kk]);
                    ffma2(acc[0][0][0], h0, wz.x); ffma2(acc[0][0][1], h0, wz.y);
                    ffma2(acc[0][1][0], h0, wv.x); ffma2(acc[0][1][1], h0, wv.y);
                    ffma2(acc[0][2][0], h0, wh.x); ffma2(acc[0][2][1], h0, wh.y);
                    ffma2(acc[1][0][0], h1, wz.x); ffma2(acc[1][0][1], h1, wz.y);
                    ffma2(acc[1][1][0], h1, wv.x); ffma2(acc[1][1][1], h1, wv.y);
                    ffma2(acc[1][2][0], h1, wh.x); ffma2(acc[1][2][1], h1, wh.y);
                }
                acur = anxt; bcur = bnxt;
            }
        }

        // ---- store partials ----
        #pragma unroll
        for (int bb = 0; bb < 2; bb++) {
            float* pr = pt + ((kg * BT + 2 * bqa + bb) * 96) + jqa;
            #pragma unroll
            for (int g = 0; g < 3; g++) {
                ulonglong2 v;
                v.x = acc[bb][g][0];
                v.y = acc[bb][g][1];
                *(ulonglong2*)(pr + g * 32) = v;
            }
        }
        __syncthreads();

        // ---- phase C: reduce 8 partials, gates, output ----
        float mz = 0.f, mr = 0.f, mh = 0.f;
        #pragma unroll
        for (int g2 = 0; g2 < 8; g2++) {
            const float* p = pt + (g2 * BT + bc) * 96 + jc;
            mz += p[0];
            mr += p[32];
            mh += p[64];
        }
        float z = sig_fast(xz + mz + bz);
        float r = sig_fast(xr + mr + br);
        float c = tanh_fast(xh + r * (mh + bh));
        float o = c + z * (hp - c);
        out[(size_t)t * BH + (size_t)(b0 + bc) * H + j0 + jc] = o;
        hp = o;

        // ---- publish ----
        __threadfence();
        __syncthreads();
        if (tid == 0) {
            *(volatile unsigned*)&g_flags[ib][jb * 32] = (unsigned)(t + 1);
        }
    }
}

// ---------------------------------------------------------------------------
// Launch
// ---------------------------------------------------------------------------
extern "C" void kernel_launch(void* const* d_in, const int* in_sizes, int n_in,
                              void* d_out, int out_size) {
    (void)in_sizes; (void)n_in; (void)out_size;
    const float* x    = (const float*)d_in[0];   // (B, T, F)
    const float* w    = (const float*)d_in[1];   // (F, 3H)
    const float* wr   = (const float*)d_in[2];   // (H, 3H)
    const float* bias = (const float*)d_in[3];   // (2, 3H)
    float* out = (float*)d_out;                  // (T, B, H)

    static int attr_set = 0;
    if (!attr_set) {
        cudaFuncSetAttribute(gru_persist,
                             cudaFuncAttributeMaxDynamicSharedMemorySize,
                             SMEM_BYTES);
        attr_set = 1;
    }

    float* mx;
    cudaGetSymbolAddress((void**)&mx, g_mx);
    void* flags;
    cudaGetSymbolAddress(&flags, g_flags);

    cudaMemsetAsync(flags, 0, sizeof(unsigned) * NBB * NJB * 32, 0);

    dim3 g1(H3 / GM_BN, (T * B) / GM_BM);        // (12, 2048)
    mx_gemm<<<g1, 256>>>(x, w, bias);

    const float* rbias = bias + H3;
    dim3 g2(NJB, NBB);                           // (8, 16) = 128 blocks
    gru_persist<<<g2, 512, SMEM_BYTES>>>(mx, wr, rbias, out);
}

// round 7
// speedup vs baseline: 1.6441x; 1.0567x over previous
#include <cuda_runtime.h>
#include <math.h>
#include <stdint.h>

#define B 256
#define T 512
#define F 128
#define H 256
#define H3 768
#define BH (B * H)

// Static device scratch for the hoisted input projection: MX[t*B+b][0..767]
__device__ float g_mx[(size_t)T * B * H3];   // ~402 MB

// Flag array for inter-block sync (one 128B line per flag)
#define NJB 8
#define NBB 16
__device__ unsigned g_flags[NBB][NJB * 32];

// ---------------------------------------------------------------------------
// Helpers
// ---------------------------------------------------------------------------
__device__ __forceinline__ void ffma2(unsigned long long &acc,
                                      unsigned long long a,
                                      unsigned long long b) {
    asm("fma.rn.f32x2 %0, %1, %2, %0;" : "+l"(acc) : "l"(a), "l"(b));
}
__device__ __forceinline__ unsigned long long dup2(float v) {
    unsigned long long r;
    asm("mov.b64 %0, {%1, %1};" : "=l"(r) : "f"(v));
    return r;
}
__device__ __forceinline__ float2 unpk(unsigned long long v) {
    float2 r;
    asm("mov.b64 {%0, %1}, %2;" : "=f"(r.x), "=f"(r.y) : "l"(v));
    return r;
}
__device__ __forceinline__ float tanh_fast(float x) {
    float y;
    asm("tanh.approx.f32 %0, %1;" : "=f"(y) : "f"(x));
    return y;
}
__device__ __forceinline__ float sig_fast(float x) {
    return fmaf(0.5f, tanh_fast(0.5f * x), 0.5f);
}
__device__ __forceinline__ unsigned ld_acq(const unsigned* p) {
    unsigned v;
    asm volatile("ld.acquire.gpu.global.u32 %0, [%1];" : "=r"(v) : "l"(p));
    return v;
}
__device__ __forceinline__ void st_rel(unsigned* p, unsigned v) {
    asm volatile("st.release.gpu.global.u32 [%0], %1;" :: "l"(p), "r"(v) : "memory");
}

// ---------------------------------------------------------------------------
// Kernel 1: MX[m, n] = x[b, t, :] @ W[:, n] + bias_in[n],  m = t*B + b
// ---------------------------------------------------------------------------
#define GM_BM 64
#define GM_BN 64
#define GM_BK 32

__global__ __launch_bounds__(256) void mx_gemm(const float* __restrict__ x,
                                               const float* __restrict__ w,
                                               const float* __restrict__ bias) {
    __shared__ float As[GM_BK][GM_BM + 4];
    __shared__ float Bs[GM_BK][GM_BN];

    const int bm = blockIdx.y * GM_BM;
    const int bn = blockIdx.x * GM_BN;
    const int tid = (int)threadIdx.x;
    const int tm = (tid >> 4) << 2;
    const int tn = (tid & 15) << 2;

    unsigned long long acc2[4][2];
    #pragma unroll
    for (int i = 0; i < 4; i++) { acc2[i][0] = 0ull; acc2[i][1] = 0ull; }

    for (int k0 = 0; k0 < F; k0 += GM_BK) {
        #pragma unroll
        for (int i = 0; i < 2; i++) {
            int idx = tid + i * 256;
            int r = idx >> 3;
            int c = (idx & 7) << 2;
            int m = bm + r;
            int t = m >> 8;
            int b = m & 255;
            float4 v = *(const float4*)&x[((size_t)b * T + t) * F + k0 + c];
            As[c + 0][r] = v.x;
            As[c + 1][r] = v.y;
            As[c + 2][r] = v.z;
            As[c + 3][r] = v.w;
        }
        #pragma unroll
        for (int i = 0; i < 2; i++) {
            int idx = tid + i * 256;
            int r = idx >> 4;
            int c = (idx & 15) << 2;
            *(float4*)&Bs[r][c] = *(const float4*)&w[(size_t)(k0 + r) * H3 + bn + c];
        }
        __syncthreads();

        #pragma unroll
        for (int k = 0; k < GM_BK; k++) {
            unsigned long long a0 = dup2(As[k][tm + 0]);
            unsigned long long a1 = dup2(As[k][tm + 1]);
            unsigned long long a2 = dup2(As[k][tm + 2]);
            unsigned long long a3 = dup2(As[k][tm + 3]);
            const unsigned long long* bsk = (const unsigned long long*)&Bs[k][tn];
            unsigned long long b01 = bsk[0];
            unsigned long long b23 = bsk[1];
            ffma2(acc2[0][0], a0, b01); ffma2(acc2[0][1], a0, b23);
            ffma2(acc2[1][0], a1, b01); ffma2(acc2[1][1], a1, b23);
            ffma2(acc2[2][0], a2, b01); ffma2(acc2[2][1], a2, b23);
            ffma2(acc2[3][0], a3, b01); ffma2(acc2[3][1], a3, b23);
        }
        __syncthreads();
    }

    float4 bz4 = *(const float4*)&bias[bn + tn];
    #pragma unroll
    for (int i = 0; i < 4; i++) {
        float2 lo = unpk(acc2[i][0]);
        float2 hi = unpk(acc2[i][1]);
        float4 o;
        o.x = lo.x + bz4.x;
        o.y = lo.y + bz4.y;
        o.z = hi.x + bz4.z;
        o.w = hi.y + bz4.w;
        *(float4*)&g_mx[(size_t)(bm + tm + i) * H3 + bn + tn] = o;
    }
}

// ---------------------------------------------------------------------------
// Kernel 2: persistent GRU recurrence.
// Grid (8 j-tiles, 16 b-tiles) = 128 blocks, 512 threads, 1 block/SM.
// Wr slice (256k x 96 gate-cols, 96KB) in smem once.
// Per step: fused poll+stage (each warp-pair owns one peer j-tile: poll its
// flag warp-uniform, LDG 2xfloat4, STS into hs), one bar, 8-way k-split
// FFMA2 compute from smem, partial reduce, gates, STG h, bar,
// st.release.gpu flag (no __threadfence).
// ---------------------------------------------------------------------------
#define BT 16
#define JT 32
#define WS_FLOATS (256 * 96)
#define HSS 260                     // h row stride (16B aligned, 4-bank skew)
#define HS_FLOATS (BT * HSS)
#define PT_FLOATS (8 * BT * 96)
#define SMEM_BYTES ((WS_FLOATS + HS_FLOATS + PT_FLOATS) * 4)

extern __shared__ float smem_dyn[];

__global__ __launch_bounds__(512, 1)
void gru_persist(const float* __restrict__ mx,
                 const float* __restrict__ wr,
                 const float* __restrict__ rbias,
                 float* __restrict__ out) {
    float* ws = smem_dyn;                         // [k=256][96]
    float* hs = ws + WS_FLOATS;                   // [16][HSS]
    float* pt = hs + HS_FLOATS;                   // [kg=8][16][96]

    const int tid = (int)threadIdx.x;             // 0..511
    const int wid = tid >> 5;                     // 0..15
    const int lane = tid & 31;
    const int jb = (int)blockIdx.x;               // 0..7
    const int ib = (int)blockIdx.y;               // 0..15
    const int b0 = ib * BT;
    const int j0 = jb * JT;

    // Phase-A mapping: kg 0..7 (32 k's each), 2 b-rows x 4 j x 3 gates
    const int kg = tid >> 6;                      // 0..7
    const int r6 = tid & 63;
    const int bqa = r6 >> 3;                      // 0..7
    const int jqa = (r6 & 7) << 2;                // 0,4,...,28

    // Phase-C mapping: one (b, j) element per thread
    const int bc = tid >> 5;                      // 0..15
    const int jc = tid & 31;                      // 0..31

    // Stage mapping: warp-pair -> peer j-tile
    const int sp   = wid >> 1;                    // peer 0..7
    const int srow = (wid & 1) * 8 + (lane >> 2); // row 0..15
    const int sc4  = lane & 3;                    // f4 col 0..3 (then +4)

    // Load Wr slice once: ws[k][g*32+jj] = wr[k][g*256 + j0 + jj]
    for (int idx = tid; idx < WS_FLOATS / 2; idx += 512) {
        int k = idx / 48;
        int c2 = idx % 48;
        int g = c2 >> 4;
        int jj = (c2 & 15) << 1;
        float2 v = *(const float2*)&wr[(size_t)k * H3 + g * H + j0 + jj];
        *(float2*)&ws[k * 96 + g * 32 + jj] = v;
    }

    const float bz = rbias[j0 + jc];
    const float br = rbias[H + j0 + jc];
    const float bh = rbias[2 * H + j0 + jc];

    // Zero hs for step 0
    for (int i = tid; i < HS_FLOATS; i += 512) hs[i] = 0.0f;
    __syncthreads();

    float hp = 0.0f;                              // carried own h element

    for (int t = 0; t < T; t++) {
        // ---- prefetch mx gate inputs (independent of flags) ----
        const float* mxr = mx + ((size_t)t * B + (b0 + bc)) * H3 + (j0 + jc);
        float xz = mxr[0];
        float xr = mxr[H];
        float xh = mxr[2 * H];

        // ---- fused poll + stage h_prev tile ----
        if (t > 0) {
            if (sp != jb) {
                const unsigned* fp = &g_flags[ib][sp * 32];
                while (ld_acq(fp) < (unsigned)t) { __nanosleep(20); }
            }
            const float* hrow = out + (size_t)(t - 1) * BH
                              + (size_t)(b0 + srow) * H + sp * 32;
            float4 v0 = *(const float4*)&hrow[sc4 * 4];
            float4 v1 = *(const float4*)&hrow[sc4 * 4 + 16];
            float* hd = hs + srow * HSS + sp * 32;
            *(float4*)&hd[sc4 * 4] = v0;
            *(float4*)&hd[sc4 * 4 + 16] = v1;
        }
        __syncthreads();

        // ---- phase A: partial mh over this k-group's 32 k's ----
        unsigned long long acc[2][3][2];
        #pragma unroll
        for (int bb = 0; bb < 2; bb++)
            #pragma unroll
            for (int g = 0; g < 3; g++) { acc[bb][g][0] = 0ull; acc[bb][g][1] = 0ull; }

        const float* h0p = hs + (2 * bqa) * HSS;
        const float* h1p = hs + (2 * bqa + 1) * HSS;
        const int k_beg = kg * 32;

        #pragma unroll 8
        for (int kk = 0; kk < 32; kk++) {
            int k = k_beg + kk;
            const float* wk = ws + k * 96 + jqa;
            ulonglong2 wz = *(const ulonglong2*)(wk);
            ulonglong2 wv = *(const ulonglong2*)(wk + 32);
            ulonglong2 wh = *(const ulonglong2*)(wk + 64);
            unsigned long long h0 = dup2(h0p[k]);
            unsigned long long h1 = dup2(h1p[k]);
            ffma2(acc[0][0][0], h0, wz.x); ffma2(acc[0][0][1], h0, wz.y);
            ffma2(acc[0][1][0], h0, wv.x); ffma2(acc[0][1][1], h0, wv.y);
            ffma2(acc[0][2][0], h0, wh.x); ffma2(acc[0][2][1], h0, wh.y);
            ffma2(acc[1][0][0], h1, wz.x); ffma2(acc[1][0][1], h1, wz.y);
            ffma2(acc[1][1][0], h1, wv.x); ffma2(acc[1][1][1], h1, wv.y);
            ffma2(acc[1][2][0], h1, wh.x); ffma2(acc[1][2][1], h1, wh.y);
        }

        // ---- store partials ----
        #pragma unroll
        for (int bb = 0; bb < 2; bb++) {
            float* pr = pt + ((kg * BT + 2 * bqa + bb) * 96) + jqa;
            #pragma unroll
            for (int g = 0; g < 3; g++) {
                ulonglong2 v;
                v.x = acc[bb][g][0];
                v.y = acc[bb][g][1];
                *(ulonglong2*)(pr + g * 32) = v;
            }
        }
        __syncthreads();

        // ---- phase C: reduce 8 partials, gates, output ----
        float mz = 0.f, mr = 0.f, mh = 0.f;
        #pragma unroll
        for (int g2 = 0; g2 < 8; g2++) {
            const float* p = pt + (g2 * BT + bc) * 96 + jc;
            mz += p[0];
            mr += p[32];
            mh += p[64];
        }
        float z = sig_fast(xz + mz + bz);
        float r = sig_fast(xr + mr + br);
        float c = tanh_fast(xh + r * (mh + bh));
        float o = c + z * (hp - c);
        out[(size_t)t * BH + (size_t)(b0 + bc) * H + j0 + jc] = o;
        hp = o;

        // ---- publish: bar orders all STGs before the release store ----
        __syncthreads();
        if (tid == 0) {
            st_rel(&g_flags[ib][jb * 32], (unsigned)(t + 1));
        }
    }
}

// ---------------------------------------------------------------------------
// Launch
// ---------------------------------------------------------------------------
extern "C" void kernel_launch(void* const* d_in, const int* in_sizes, int n_in,
                              void* d_out, int out_size) {
    (void)in_sizes; (void)n_in; (void)out_size;
    const float* x    = (const float*)d_in[0];   // (B, T, F)
    const float* w    = (const float*)d_in[1];   // (F, 3H)
    const float* wr   = (const float*)d_in[2];   // (H, 3H)
    const float* bias = (const float*)d_in[3];   // (2, 3H)
    float* out = (float*)d_out;                  // (T, B, H)

    static int attr_set = 0;
    if (!attr_set) {
        cudaFuncSetAttribute(gru_persist,
                             cudaFuncAttributeMaxDynamicSharedMemorySize,
                             SMEM_BYTES);
        attr_set = 1;
    }

    float* mx;
    cudaGetSymbolAddress((void**)&mx, g_mx);
    void* flags;
    cudaGetSymbolAddress(&flags, g_flags);

    cudaMemsetAsync(flags, 0, sizeof(unsigned) * NBB * NJB * 32, 0);

    dim3 g1(H3 / GM_BN, (T * B) / GM_BM);        // (12, 2048)
    mx_gemm<<<g1, 256>>>(x, w, bias);

    const float* rbias = bias + H3;
    dim3 g2(NJB, NBB);                           // (8, 16) = 128 blocks
    gru_persist<<<g2, 512, SMEM_BYTES>>>(mx, wr, rbias, out);
}

// round 8
// speedup vs baseline: 1.6479x; 1.0023x over previous
#include <cuda_runtime.h>
#include <math.h>
#include <stdint.h>

#define B 256
#define T 512
#define F 128
#define H 256
#define H3 768
#define BH (B * H)

// Static device scratch for the hoisted input projection: MX[t*B+b][0..767]
__device__ float g_mx[(size_t)T * B * H3];   // ~402 MB

// Flag array for inter-block sync (one 128B line per flag)
#define NJB 8
#define NBB 16
__device__ unsigned g_flags[NBB][NJB * 32];

// ---------------------------------------------------------------------------
// Helpers
// ---------------------------------------------------------------------------
__device__ __forceinline__ void ffma2(unsigned long long &acc,
                                      unsigned long long a,
                                      unsigned long long b) {
    asm("fma.rn.f32x2 %0, %1, %2, %0;" : "+l"(acc) : "l"(a), "l"(b));
}
__device__ __forceinline__ unsigned long long dup2(float v) {
    unsigned long long r;
    asm("mov.b64 %0, {%1, %1};" : "=l"(r) : "f"(v));
    return r;
}
__device__ __forceinline__ float2 unpk(unsigned long long v) {
    float2 r;
    asm("mov.b64 {%0, %1}, %2;" : "=f"(r.x), "=f"(r.y) : "l"(v));
    return r;
}
__device__ __forceinline__ float tanh_fast(float x) {
    float y;
    asm("tanh.approx.f32 %0, %1;" : "=f"(y) : "f"(x));
    return y;
}
__device__ __forceinline__ float sig_fast(float x) {
    return fmaf(0.5f, tanh_fast(0.5f * x), 0.5f);
}
__device__ __forceinline__ unsigned ld_acq(const unsigned* p) {
    unsigned v;
    asm volatile("ld.acquire.gpu.global.u32 %0, [%1];" : "=r"(v) : "l"(p));
    return v;
}
__device__ __forceinline__ void st_rel(unsigned* p, unsigned v) {
    asm volatile("st.release.gpu.global.u32 [%0], %1;" :: "l"(p), "r"(v) : "memory");
}

// ---------------------------------------------------------------------------
// Kernel 1: MX[m, n] = x[b, t, :] @ W[:, n] + bias_in[n],  m = t*B + b
// ---------------------------------------------------------------------------
#define GM_BM 64
#define GM_BN 64
#define GM_BK 32

__global__ __launch_bounds__(256) void mx_gemm(const float* __restrict__ x,
                                               const float* __restrict__ w,
                                               const float* __restrict__ bias) {
    __shared__ float As[GM_BK][GM_BM + 4];
    __shared__ float Bs[GM_BK][GM_BN];

    const int bm = blockIdx.y * GM_BM;
    const int bn = blockIdx.x * GM_BN;
    const int tid = (int)threadIdx.x;
    const int tm = (tid >> 4) << 2;
    const int tn = (tid & 15) << 2;

    unsigned long long acc2[4][2];
    #pragma unroll
    for (int i = 0; i < 4; i++) { acc2[i][0] = 0ull; acc2[i][1] = 0ull; }

    for (int k0 = 0; k0 < F; k0 += GM_BK) {
        #pragma unroll
        for (int i = 0; i < 2; i++) {
            int idx = tid + i * 256;
            int r = idx >> 3;
            int c = (idx & 7) << 2;
            int m = bm + r;
            int t = m >> 8;
            int b = m & 255;
            float4 v = *(const float4*)&x[((size_t)b * T + t) * F + k0 + c];
            As[c + 0][r] = v.x;
            As[c + 1][r] = v.y;
            As[c + 2][r] = v.z;
            As[c + 3][r] = v.w;
        }
        #pragma unroll
        for (int i = 0; i < 2; i++) {
            int idx = tid + i * 256;
            int r = idx >> 4;
            int c = (idx & 15) << 2;
            *(float4*)&Bs[r][c] = *(const float4*)&w[(size_t)(k0 + r) * H3 + bn + c];
        }
        __syncthreads();

        #pragma unroll
        for (int k = 0; k < GM_BK; k++) {
            unsigned long long a0 = dup2(As[k][tm + 0]);
            unsigned long long a1 = dup2(As[k][tm + 1]);
            unsigned long long a2 = dup2(As[k][tm + 2]);
            unsigned long long a3 = dup2(As[k][tm + 3]);
            const unsigned long long* bsk = (const unsigned long long*)&Bs[k][tn];
            unsigned long long b01 = bsk[0];
            unsigned long long b23 = bsk[1];
            ffma2(acc2[0][0], a0, b01); ffma2(acc2[0][1], a0, b23);
            ffma2(acc2[1][0], a1, b01); ffma2(acc2[1][1], a1, b23);
            ffma2(acc2[2][0], a2, b01); ffma2(acc2[2][1], a2, b23);
            ffma2(acc2[3][0], a3, b01); ffma2(acc2[3][1], a3, b23);
        }
        __syncthreads();
    }

    float4 bz4 = *(const float4*)&bias[bn + tn];
    #pragma unroll
    for (int i = 0; i < 4; i++) {
        float2 lo = unpk(acc2[i][0]);
        float2 hi = unpk(acc2[i][1]);
        float4 o;
        o.x = lo.x + bz4.x;
        o.y = lo.y + bz4.y;
        o.z = hi.x + bz4.z;
        o.w = hi.y + bz4.w;
        *(float4*)&g_mx[(size_t)(bm + tm + i) * H3 + bn + tn] = o;
    }
}

// ---------------------------------------------------------------------------
// Kernel 2: persistent GRU recurrence, overlapped producer/consumer version.
// Grid (8 j-tiles, 16 b-tiles) = 128 blocks, 512 threads, 1 block/SM.
// Wr slice (256k x 96 gate-cols, 96KB) in smem once.
// Per step:
//  - 14 stager warps: poll own peer's flag (lane0), LDG its 16x32 h tile,
//    STS into double-buffered hs, bump per-peer smem counter. Independent.
//  - 8 compute groups (64 thr): group kg spins on counter[kg] only
//    (own group kg==jb never waits; its tile was STS'd by phase C last step).
//  - partial store, bar, reduce+gates, STG out + STS own h to next buffer,
//    bar, st.release flag.
// ---------------------------------------------------------------------------
#define BT 16
#define JT 32
#define WS_FLOATS (256 * 96)
#define HSS 260                     // h row stride (16B aligned, 4-bank skew)
#define HS_FLOATS (BT * HSS)
#define PT_FLOATS (8 * BT * 96)
#define SMEM_BYTES ((WS_FLOATS + 2 * HS_FLOATS + PT_FLOATS) * 4 + 64)

extern __shared__ float smem_dyn[];

__global__ __launch_bounds__(512, 1)
void gru_persist(const float* __restrict__ mx,
                 const float* __restrict__ wr,
                 const float* __restrict__ rbias,
                 float* __restrict__ out) {
    float* ws = smem_dyn;                         // [k=256][96]
    float* hs = ws + WS_FLOATS;                   // [2][16][HSS]
    float* pt = hs + 2 * HS_FLOATS;               // [kg=8][16][96]
    unsigned* cnt = (unsigned*)(pt + PT_FLOATS);  // [2][8] monotonic counters

    const int tid = (int)threadIdx.x;             // 0..511
    const int wid = tid >> 5;                     // 0..15
    const int lane = tid & 31;
    const int jb = (int)blockIdx.x;               // 0..7
    const int ib = (int)blockIdx.y;               // 0..15
    const int b0 = ib * BT;
    const int j0 = jb * JT;

    // Phase-A mapping: kg 0..7 (32 k's each), 2 b-rows x 4 j x 3 gates
    const int kg = tid >> 6;                      // 0..7
    const int r6 = tid & 63;
    const int bqa = r6 >> 3;                      // 0..7
    const int jqa = (r6 & 7) << 2;                // 0,4,...,28

    // Phase-C mapping: one (b, j) element per thread
    const int bc = tid >> 5;                      // 0..15
    const int jc = tid & 31;                      // 0..31

    // Stager mapping: warps 0..13, pair (w>>1) -> peer; 8 rows per warp
    const int speer = (jb + 1 + (wid >> 1)) & 7;  // staged peer j-tile
    const int srow  = (wid & 1) * 8 + (lane >> 2);// row 0..15
    const int sc4   = lane & 3;                   // f4 col 0..3 (then +4)

    // Load Wr slice once: ws[k][g*32+jj] = wr[k][g*256 + j0 + jj]
    for (int idx = tid; idx < WS_FLOATS / 2; idx += 512) {
        int k = idx / 48;
        int c2 = idx % 48;
        int g = c2 >> 4;
        int jj = (c2 & 15) << 1;
        float2 v = *(const float2*)&wr[(size_t)k * H3 + g * H + j0 + jj];
        *(float2*)&ws[k * 96 + g * 32 + jj] = v;
    }
    if (tid < 16) cnt[tid] = 0u;

    const float bz = rbias[j0 + jc];
    const float br = rbias[H + j0 + jc];
    const float bh = rbias[2 * H + j0 + jc];
    __syncthreads();

    float hp = 0.0f;                              // carried own h element

    for (int t = 0; t < T; t++) {
        // ---- prefetch mx gate inputs (independent of everything) ----
        const float* mxr = mx + ((size_t)t * B + (b0 + bc)) * H3 + (j0 + jc);
        float xz = mxr[0];
        float xr = mxr[H];
        float xh = mxr[2 * H];

        const int buf = t & 1;
        float* hsb = hs + buf * HS_FLOATS;

        unsigned long long acc[2][3][2];
        #pragma unroll
        for (int bb = 0; bb < 2; bb++)
            #pragma unroll
            for (int g = 0; g < 3; g++) { acc[bb][g][0] = 0ull; acc[bb][g][1] = 0ull; }

        if (t > 0) {
            // ---- stage: each warp-pair handles one peer tile, independently --
            if (wid < 14) {
                if (lane == 0) {
                    const unsigned* fp = &g_flags[ib][speer * 32];
                    while (ld_acq(fp) < (unsigned)t) { __nanosleep(20); }
                }
                __syncwarp();
                const float* hrow = out + (size_t)(t - 1) * BH
                                  + (size_t)(b0 + srow) * H + speer * 32;
                float4 v0 = *(const float4*)&hrow[sc4 * 4];
                float4 v1 = *(const float4*)&hrow[sc4 * 4 + 16];
                float* hd = hsb + srow * HSS + speer * 32;
                *(float4*)&hd[sc4 * 4] = v0;
                *(float4*)&hd[sc4 * 4 + 16] = v1;
                __syncwarp();
                if (lane == 0) {
                    __threadfence_block();
                    atomicAdd(&cnt[buf * 8 + speer], 1u);
                }
            }

            // ---- consume: wait only for this group's chunk ----
            if (kg != jb) {
                const unsigned tgt = (unsigned)(t + (t & 1));
                volatile unsigned* cp = &cnt[buf * 8 + kg];
                while (*cp < tgt) { __nanosleep(16); }
                __threadfence_block();
            }

            // ---- phase A: partial mh over this group's 32 k's ----
            const float* h0p = hsb + (2 * bqa) * HSS;
            const float* h1p = h0p + HSS;
            const int k_beg = kg * 32;

            #pragma unroll
            for (int kk = 0; kk < 32; kk += 4) {
                float4 ha4 = *(const float4*)&h0p[k_beg + kk];
                float4 hb4 = *(const float4*)&h1p[k_beg + kk];
                float ha[4] = {ha4.x, ha4.y, ha4.z, ha4.w};
                float hb[4] = {hb4.x, hb4.y, hb4.z, hb4.w};
                #pragma unroll
                for (int u = 0; u < 4; u++) {
                    const float* wk = ws + (size_t)(k_beg + kk + u) * 96 + jqa;
                    ulonglong2 wz = *(const ulonglong2*)(wk);
                    ulonglong2 wv = *(const ulonglong2*)(wk + 32);
                    ulonglong2 wh = *(const ulonglong2*)(wk + 64);
                    unsigned long long h0 = dup2(ha[u]);
                    unsigned long long h1 = dup2(hb[u]);
                    ffma2(acc[0][0][0], h0, wz.x); ffma2(acc[0][0][1], h0, wz.y);
                    ffma2(acc[0][1][0], h0, wv.x); ffma2(acc[0][1][1], h0, wv.y);
                    ffma2(acc[0][2][0], h0, wh.x); ffma2(acc[0][2][1], h0, wh.y);
                    ffma2(acc[1][0][0], h1, wz.x); ffma2(acc[1][0][1], h1, wz.y);
                    ffma2(acc[1][1][0], h1, wv.x); ffma2(acc[1][1][1], h1, wv.y);
                    ffma2(acc[1][2][0], h1, wh.x); ffma2(acc[1][2][1], h1, wh.y);
                }
            }
        }

        // ---- store partials ----
        #pragma unroll
        for (int bb = 0; bb < 2; bb++) {
            float* pr = pt + ((kg * BT + 2 * bqa + bb) * 96) + jqa;
            #pragma unroll
            for (int g = 0; g < 3; g++) {
                ulonglong2 v;
                v.x = acc[bb][g][0];
                v.y = acc[bb][g][1];
                *(ulonglong2*)(pr + g * 32) = v;
            }
        }
        __syncthreads();

        // ---- phase C: reduce 8 partials, gates, output ----
        float mz = 0.f, mr = 0.f, mh = 0.f;
        #pragma unroll
        for (int g2 = 0; g2 < 8; g2++) {
            const float* p = pt + (g2 * BT + bc) * 96 + jc;
            mz += p[0];
            mr += p[32];
            mh += p[64];
        }
        float z = sig_fast(xz + mz + bz);
        float r = sig_fast(xr + mr + br);
        float c = tanh_fast(xh + r * (mh + bh));
        float o = c + z * (hp - c);
        out[(size_t)t * BH + (size_t)(b0 + bc) * H + j0 + jc] = o;
        // own tile for next step: straight to smem, no L2 round trip
        hs[(buf ^ 1) * HS_FLOATS + bc * HSS + j0 + jc] = o;
        hp = o;

        // ---- publish: bar orders all STGs (and own STS) before release ----
        __syncthreads();
        if (tid == 0) {
            st_rel(&g_flags[ib][jb * 32], (unsigned)(t + 1));
        }
    }
}

// ---------------------------------------------------------------------------
// Launch
// ---------------------------------------------------------------------------
extern "C" void kernel_launch(void* const* d_in, const int* in_sizes, int n_in,
                              void* d_out, int out_size) {
    (void)in_sizes; (void)n_in; (void)out_size;
    const float* x    = (const float*)d_in[0];   // (B, T, F)
    const float* w    = (const float*)d_in[1];   // (F, 3H)
    const float* wr   = (const float*)d_in[2];   // (H, 3H)
    const float* bias = (const float*)d_in[3];   // (2, 3H)
    float* out = (float*)d_out;                  // (T, B, H)

    static int attr_set = 0;
    if (!attr_set) {
        cudaFuncSetAttribute(gru_persist,
                             cudaFuncAttributeMaxDynamicSharedMemorySize,
                             SMEM_BYTES);
        attr_set = 1;
    }

    float* mx;
    cudaGetSymbolAddress((void**)&mx, g_mx);
    void* flags;
    cudaGetSymbolAddress(&flags, g_flags);

    cudaMemsetAsync(flags, 0, sizeof(unsigned) * NBB * NJB * 32, 0);

    dim3 g1(H3 / GM_BN, (T * B) / GM_BM);        // (12, 2048)
    mx_gemm<<<g1, 256>>>(x, w, bias);

    const float* rbias = bias + H3;
    dim3 g2(NJB, NBB);                           // (8, 16) = 128 blocks
    gru_persist<<<g2, 512, SMEM_BYTES>>>(mx, wr, rbias, out);
}